// round 6
// baseline (speedup 1.0000x reference)
#include <cuda_runtime.h>
#include <cstdint>

#define NN 16
#define WD 64
#define TILE 32
#define NT 256
#define BUF 2048                 // [64 feat][32 samples] floats, XOR-swizzled (8 KB)
#define WSH 4096                 // transposed weights: [64 k][64 o] floats (16 KB)
#define NSTEP 17

struct Plan {
    int nslot;
    int encSlot, aggSlot;
    int srcSlot[NSTEP];
    int sumSlot[NSTEP];
    int outSlot[NSTEP];
    int accum[NSTEP];
    int act[NSTEP];
    int nPreds[NSTEP];
    unsigned char predSlot[NSTEP][NN];
};

// ---------------- device helpers ----------------

__device__ __forceinline__ unsigned long long pk2(float x) {
    unsigned long long r; unsigned xi = __float_as_uint(x);
    asm("mov.b64 %0, {%1, %1};" : "=l"(r) : "r"(xi));
    return r;
}
__device__ __forceinline__ void upk2(unsigned long long v, float& lo, float& hi) {
    unsigned a, b;
    asm("mov.b64 {%0, %1}, %2;" : "=r"(a), "=r"(b) : "l"(v));
    lo = __uint_as_float(a); hi = __uint_as_float(b);
}
__device__ __forceinline__ void ffma2(unsigned long long& acc,
                                      unsigned long long a, unsigned long long b) {
    asm("fma.rn.f32x2 %0, %1, %2, %0;" : "+l"(acc) : "l"(a), "l"(b));
}

// swizzled word index for (feature f, sample s) in a [64][32] buffer
__device__ __forceinline__ int swidx(int f, int s) {
    return f * 32 + ((((s >> 2) ^ f) & 7) << 2) + (s & 3);
}
// float4-quad offset for (feature f, sample-quad s4)
__device__ __forceinline__ int swq(int f, int s4) {
    return f * 32 + (((s4 ^ f) & 7) << 2);
}

__device__ __forceinline__ float fast_tanh(float x) {
    float e = __expf(2.f * x);
    return 1.f - __fdividef(2.f, e + 1.f);
}

// GRAPH_ACTS = [tanh, elu, softplus, sin, gaussian] — fast intrinsic forms
__device__ __forceinline__ float actf(int id, float v) {
    switch (id) {
        case 0:  return fast_tanh(v);
        case 1:  return v > 0.f ? v : (__expf(v) - 1.f);
        case 2:  return fmaxf(v, 0.f) + __logf(1.f + __expf(-fabsf(v)));
        case 3:  return __sinf(v);
        default: return __expf(-0.5f * v * v);
    }
}

// prefetch: thread t loads o = t&63, k-quarter (t>>6)*16 : 4 float4 (64 B)
__device__ __forceinline__ void ldg_w(const float* __restrict__ gw, float4* wp, int t) {
    const float4* src = (const float4*)(gw + (t & 63) * 64 + (t >> 6) * 16);
#pragma unroll
    for (int q = 0; q < 4; q++) wp[q] = src[q];
}
// store transposed into shared: wsh[k*64 + o] (lanes span o -> conflict-free)
__device__ __forceinline__ void sts_w(const float4* wp, float* __restrict__ wsh, int t) {
    int o  = t & 63;
    int kb = (t >> 6) * 16;
#pragma unroll
    for (int q = 0; q < 4; q++) {
        int k = kb + q * 4;
        wsh[(k + 0) * 64 + o] = wp[q].x;
        wsh[(k + 1) * 64 + o] = wp[q].y;
        wsh[(k + 2) * 64 + o] = wp[q].z;
        wsh[(k + 3) * 64 + o] = wp[q].w;
    }
}

// GEMM: thread (sq 0..7, ot 0..31): samples sq*4..+3 x outputs ot*2, ot*2+1
__device__ __forceinline__ void gemm64(const float* __restrict__ in,
                                       const float* __restrict__ wsh,
                                       const float* __restrict__ bias_g,
                                       int actId, float* __restrict__ outp,
                                       bool accum, int sq, int ot) {
    unsigned long long a00 = 0, a01 = 0, a10 = 0, a11 = 0;

    // 8 XOR base pointers (c = k&7), resolved statically by the unroll
    const float* ab[8];
#pragma unroll
    for (int c = 0; c < 8; c++) ab[c] = in + (((sq ^ c) & 7) << 2);
    const float* wq = wsh + ot * 2;

#pragma unroll 16
    for (int k = 0; k < 64; k++) {
        ulonglong2 av = *(const ulonglong2*)(ab[k & 7] + k * 32);  // 4 acts
        float2 wv = *(const float2*)(wq + k * 64);                 // 2 weights (bcast)
        unsigned long long w0 = pk2(wv.x), w1 = pk2(wv.y);
        ffma2(a00, av.x, w0); ffma2(a01, av.y, w0);
        ffma2(a10, av.x, w1); ffma2(a11, av.y, w1);
    }
    float2 bv = *(const float2*)(bias_g + ot * 2);
    float r0, r1, r2, r3, q0, q1, q2, q3;
    upk2(a00, r0, r1); upk2(a01, r2, r3);
    upk2(a10, q0, q1); upk2(a11, q2, q3);
    float4 o0, o1;
    o0.x = actf(actId, r0 + bv.x); o0.y = actf(actId, r1 + bv.x);
    o0.z = actf(actId, r2 + bv.x); o0.w = actf(actId, r3 + bv.x);
    o1.x = actf(actId, q0 + bv.y); o1.y = actf(actId, q1 + bv.y);
    o1.z = actf(actId, q2 + bv.y); o1.w = actf(actId, q3 + bv.y);
    float* p0 = outp + swq(ot * 2, sq);
    float* p1 = outp + swq(ot * 2 + 1, sq);
    if (accum) {
        float4 c0 = *(const float4*)p0, c1 = *(const float4*)p1;
        o0.x += c0.x; o0.y += c0.y; o0.z += c0.z; o0.w += c0.w;
        o1.x += c1.x; o1.y += c1.y; o1.z += c1.z; o1.w += c1.w;
    }
    *(float4*)p0 = o0; *(float4*)p1 = o1;
}

// ---------------- kernel ----------------

__global__ void __launch_bounds__(NT, 2)
inr_kernel(const float* __restrict__ inp, const float* __restrict__ lats,
           const float* __restrict__ Wl, const float* __restrict__ bl,
           const float* __restrict__ Wx, const float* __restrict__ Wy,
           const float* __restrict__ Wr, const float* __restrict__ W1,
           const float* __restrict__ b1, const float* __restrict__ gW,
           const float* __restrict__ gB, const float* __restrict__ outW,
           const float* __restrict__ outb, const float* __restrict__ scale,
           float* __restrict__ out, Plan pl) {
    extern __shared__ float sm[];
    float* w_sh = sm;            // WSH floats (16 KB)
    float* bufs = sm + WSH;      // nslot * BUF

    const int t  = threadIdx.x;
    const int sq = t & 7;
    const int ot = t >> 3;       // 0..31
    const int s  = t & 31;
    const int og = t >> 5;       // 0..7
    const int gsb = blockIdx.x * TILE;

    float4 wpf[4];
    ldg_w(W1, wpf, t);

    // ---- encode -> bufs[encSlot]: thread (s, og) does 8 outputs for sample s ----
    {
        float* enc = bufs + pl.encSlot * BUF;
        int gs = gsb + s;
        float xs = inp[gs * 3 + 0], ys = inp[gs * 3 + 1], rs = inp[gs * 3 + 2];
        float lat[8];
        const float4* lp = (const float4*)(lats + gs * 8);
        float4 l0 = lp[0], l1 = lp[1];
        lat[0] = l0.x; lat[1] = l0.y; lat[2] = l0.z; lat[3] = l0.w;
        lat[4] = l1.x; lat[5] = l1.y; lat[6] = l1.z; lat[7] = l1.w;
#pragma unroll
        for (int i = 0; i < 8; i++) {
            int o = og * 8 + i;
            float pre = bl[o];
#pragma unroll
            for (int k = 0; k < 8; k++) pre = fmaf(lat[k], Wl[o * 8 + k], pre);
            float lv = fast_tanh(pre);
            float xv = fast_tanh(xs * Wx[o]);
            float yv; { float z = ys * Wy[o]; yv = fmaxf(z, 0.f) + __logf(1.f + __expf(-fabsf(z))); }
            float rv; { float z = rs * Wr[o]; rv = z > 0.f ? z : (__expf(z) - 1.f); }
            float u = xv + yv + rv + lv;
            enc[swidx(o, s)] = __expf(-0.5f * u * u);
        }
    }

    // ---- 17 GEMM steps ----
    for (int st = 0; st < NSTEP; st++) {
        __syncthreads();                 // prev gemm done: w_sh reusable, outputs visible
        sts_w(wpf, w_sh, t);
        if (st < NSTEP - 1) ldg_w(gW + st * 4096, wpf, t);

        int ss = pl.srcSlot[st];
        if (ss < 0) {                    // multi-pred sum -> sumSlot
            int np = pl.nPreds[st];
            const float* p0 = bufs + pl.predSlot[st][0] * BUF;
            float* dst = bufs + pl.sumSlot[st] * BUF;
#pragma unroll 2
            for (int q = t; q < 512; q += NT) {
                int off = swq(q >> 3, q & 7);
                float4 v = *(const float4*)(p0 + off);
                for (int p = 1; p < np; p++) {
                    float4 u = *(const float4*)(bufs + pl.predSlot[st][p] * BUF + off);
                    v.x += u.x; v.y += u.y; v.z += u.z; v.w += u.w;
                }
                *(float4*)(dst + off) = v;
            }
            ss = pl.sumSlot[st];
        }
        __syncthreads();                 // weights + src visible

        const float* bias = (st == 0) ? b1 : gB + (st - 1) * 64;
        gemm64(bufs + ss * BUF, w_sh, bias, pl.act[st],
               bufs + pl.outSlot[st] * BUF, pl.accum[st] != 0, sq, ot);
    }
    __syncthreads();

    // ---- head: sigmoid((agg @ outW.T + outb) * scale) ----
    if (og < 3) {
        float acc = outb[og];
        const float* wr = outW + og * 64;
        const float* ip = bufs + pl.aggSlot * BUF;
#pragma unroll 8
        for (int k = 0; k < 64; k++) acc = fmaf(ip[swidx(k, s)], wr[k], acc);
        acc *= scale[0];
        out[(gsb + s) * 3 + og] = __fdividef(1.f, 1.f + __expf(-acc));
    }
}

// ---------------- host: graph replication + slot plan ----------------

namespace {

struct MT19937 {
    uint32_t mt[624];
    int mti;
    void seed(uint32_t s) {
        mt[0] = s;
        for (int i = 1; i < 624; i++)
            mt[i] = 1812433253u * (mt[i - 1] ^ (mt[i - 1] >> 30)) + (uint32_t)i;
        mti = 624;
    }
    uint32_t next32() {
        if (mti >= 624) {
            for (int i = 0; i < 624; i++) {
                uint32_t y = (mt[i] & 0x80000000u) | (mt[(i + 1) % 624] & 0x7fffffffu);
                uint32_t v = mt[(i + 397) % 624] ^ (y >> 1);
                if (y & 1u) v ^= 0x9908b0dfu;
                mt[i] = v;
            }
            mti = 0;
        }
        uint32_t y = mt[mti++];
        y ^= y >> 11;
        y ^= (y << 7)  & 0x9d2c5680u;
        y ^= (y << 15) & 0xefc60000u;
        y ^= y >> 18;
        return y;
    }
    double rnd() {
        uint32_t a = next32() >> 5, b = next32() >> 6;
        return (a * 67108864.0 + b) / 9007199254740992.0;
    }
    uint32_t randint(uint32_t n) {
        uint32_t rng = n - 1;
        if (rng == 0) return 0;
        uint32_t mask = rng;
        mask |= mask >> 1; mask |= mask >> 2; mask |= mask >> 4;
        mask |= mask >> 8; mask |= mask >> 16;
        uint32_t v;
        do { v = next32() & mask; } while (v > rng);
        return v;
    }
};

void build_plan(Plan& P) {
    MT19937 rng; rng.seed(0u);
    const int n = NN;
    bool adj[NN][NN] = {};
    for (int i = 0; i < n; i++) {
        for (int d = 1; d <= 2; d++) {
            int j = (i + d) % n;
            if (rng.rnd() < 0.75) j = (int)rng.randint((uint32_t)n);
            int a = i < j ? i : j, b = i < j ? j : i;
            if (a != b) adj[a][b] = true;
        }
    }
    unsigned pm[NN] = {};
    for (int a = 0; a < n; a++)
        for (int b = 0; b < n; b++)
            if (adj[a][b]) pm[b] |= 1u << a;
    for (int j = 1; j < n; j++) {
        if (!pm[j]) {
            uint32_t a = rng.randint((uint32_t)j);
            adj[a][j] = true;
            pm[j] |= 1u << a;
        }
    }
    bool isSink[NN];
    for (int j = 0; j < n; j++) {
        bool has_succ = false;
        for (int b = 0; b < n; b++) if (adj[j][b]) has_succ = true;
        isSink[j] = !has_succ;
    }

    int uses[18] = {0};
    uses[17] = 1;
    for (int j = 0; j < n; j++) {
        if (pm[j] == 0) uses[16]++;
        else for (int i = 0; i < n; i++) if ((pm[j] >> i) & 1) uses[i]++;
    }
    int freeS[24], nFree = 0, ns = 0;
    auto alloc = [&]() { return nFree ? freeS[--nFree] : ns++; };
    auto release = [&](int sl) { freeS[nFree++] = sl; };
    int slotOf[18];

    P.aggSlot = -1;
    slotOf[17] = alloc();
    P.encSlot = slotOf[17];

    P.srcSlot[0] = slotOf[17]; P.sumSlot[0] = -1; P.nPreds[0] = 0;
    P.act[0] = 3; P.accum[0] = 0;
    slotOf[16] = alloc();
    P.outSlot[0] = slotOf[16];
    if (--uses[17] == 0) release(slotOf[17]);

    for (int j = 0; j < n; j++) {
        int st = j + 1;
        P.act[st] = j % 5;
        P.sumSlot[st] = -1; P.nPreds[st] = 0;
        int np = 0;
        for (int i = 0; i < n; i++) if ((pm[j] >> i) & 1) np++;

        int srcVal = -1;
        if (np == 0) {
            srcVal = 16;
            P.srcSlot[st] = slotOf[16];
        } else if (np == 1) {
            int p = 0; while (!((pm[j] >> p) & 1)) p++;
            srcVal = p;
            P.srcSlot[st] = slotOf[p];
        } else {
            P.srcSlot[st] = -1; P.nPreds[st] = np;
            int c = 0;
            for (int i = 0; i < n; i++)
                if ((pm[j] >> i) & 1) P.predSlot[st][c++] = (unsigned char)slotOf[i];
            for (int i = 0; i < n; i++)
                if ((pm[j] >> i) & 1) { if (--uses[i] == 0) release(slotOf[i]); }
            P.sumSlot[st] = alloc();
        }

        if (isSink[j]) {
            if (P.aggSlot < 0) { P.aggSlot = alloc(); P.accum[st] = 0; }
            else P.accum[st] = 1;
            P.outSlot[st] = P.aggSlot;
        } else {
            P.accum[st] = 0;
            slotOf[j] = alloc();
            P.outSlot[st] = slotOf[j];
        }

        if (np > 1) release(P.sumSlot[st]);
        else if (--uses[srcVal] == 0) release(slotOf[srcVal]);
    }
    P.nslot = ns;
}

}  // namespace

// ---------------- launch ----------------

extern "C" void kernel_launch(void* const* d_in, const int* in_sizes, int n_in,
                              void* d_out, int out_size) {
    (void)n_in; (void)out_size;
    Plan pl;
    build_plan(pl);

    const int B = in_sizes[0] / 3;
    const int ntiles = B / TILE;

    const size_t smem = (size_t)(WSH + pl.nslot * BUF) * sizeof(float);
    cudaFuncSetAttribute(inr_kernel, cudaFuncAttributeMaxDynamicSharedMemorySize,
                         (int)smem);

    inr_kernel<<<ntiles, NT, smem>>>(
        (const float*)d_in[0],  (const float*)d_in[1],  (const float*)d_in[2],
        (const float*)d_in[3],  (const float*)d_in[4],  (const float*)d_in[5],
        (const float*)d_in[6],  (const float*)d_in[7],  (const float*)d_in[8],
        (const float*)d_in[9],  (const float*)d_in[10], (const float*)d_in[11],
        (const float*)d_in[12], (const float*)d_in[13], (float*)d_out, pl);
}

// round 8
// speedup vs baseline: 1.0898x; 1.0898x over previous
#include <cuda_runtime.h>
#include <cstdint>

#define NN 16
#define TILE 64
#define NT 256
#define BUF 4096                 // [64 feat][64 samp] floats, parity-split rows (16 KB)
#define WSH 4096                 // transposed weights [64 k][64 o] (16 KB)
#define NSTEP 17

struct Plan {
    int nslot;
    int encSlot;
    int srcSlot[NSTEP];          // -1 => multi-pred sum into sumSlot
    int sumSlot[NSTEP];
    int outSlot[NSTEP];          // -1 => sink: accumulate in registers
    int act[NSTEP];
    int nPreds[NSTEP];
    unsigned char predSlot[NSTEP][NN];
};

// ---------------- device helpers ----------------

__device__ __forceinline__ unsigned long long pk2(float x) {
    unsigned long long r; unsigned xi = __float_as_uint(x);
    asm("mov.b64 %0, {%1, %1};" : "=l"(r) : "r"(xi));
    return r;
}
__device__ __forceinline__ void upk2(unsigned long long v, float& lo, float& hi) {
    unsigned a, b;
    asm("mov.b64 {%0, %1}, %2;" : "=r"(a), "=r"(b) : "l"(v));
    lo = __uint_as_float(a); hi = __uint_as_float(b);
}
__device__ __forceinline__ void ffma2(unsigned long long& acc,
                                      unsigned long long a, unsigned long long b) {
    asm("fma.rn.f32x2 %0, %1, %2, %0;" : "+l"(acc) : "l"(a), "l"(b));
}

// parity-split physical float index for (feature f, sample s) in a [64][64] row:
// 16B chunk c = s>>2 ; even chunks -> first 128B half (pos c/2), odd -> second half
__device__ __forceinline__ int pidx(int f, int s) {
    int c = s >> 2;
    int p = ((c & 1) << 3) | (c >> 1);
    return f * 64 + p * 4 + (s & 3);
}

__device__ __forceinline__ float fast_tanh(float x) {
    float e = __expf(2.f * x);
    return 1.f - __fdividef(2.f, e + 1.f);
}
// GRAPH_ACTS = [tanh, elu, softplus, sin, gaussian]
__device__ __forceinline__ float actf(int id, float v) {
    switch (id) {
        case 0:  return fast_tanh(v);
        case 1:  return v > 0.f ? v : (__expf(v) - 1.f);
        case 2:  return fmaxf(v, 0.f) + __logf(1.f + __expf(-fabsf(v)));
        case 3:  return __sinf(v);
        default: return __expf(-0.5f * v * v);
    }
}

// prefetch weights: thread t loads row o=t&63, k-quarter t>>6 (16 floats = 64B)
__device__ __forceinline__ void ldg_w(const float* __restrict__ gw, float4* wp, int t) {
    const float4* src = (const float4*)(gw + (t & 63) * 64 + (t >> 6) * 16);
#pragma unroll
    for (int q = 0; q < 4; q++) wp[q] = src[q];
}
// store transposed into shared: wsh[k*64 + o] (lanes span o -> 1 wf per store)
__device__ __forceinline__ void sts_w(const float4* wp, float* __restrict__ wsh, int t) {
    int o  = t & 63;
    int kb = (t >> 6) * 16;
#pragma unroll
    for (int q = 0; q < 4; q++) {
        int k = kb + q * 4;
        wsh[(k + 0) * 64 + o] = wp[q].x;
        wsh[(k + 1) * 64 + o] = wp[q].y;
        wsh[(k + 2) * 64 + o] = wp[q].z;
        wsh[(k + 3) * 64 + o] = wp[q].w;
    }
}

// ---------------- kernel ----------------

__global__ void __launch_bounds__(NT, 1)
inr_kernel(const float* __restrict__ inp, const float* __restrict__ lats,
           const float* __restrict__ Wl, const float* __restrict__ bl,
           const float* __restrict__ Wx, const float* __restrict__ Wy,
           const float* __restrict__ Wr, const float* __restrict__ W1,
           const float* __restrict__ b1, const float* __restrict__ gW,
           const float* __restrict__ gB, const float* __restrict__ outW,
           const float* __restrict__ outb, const float* __restrict__ scale,
           float* __restrict__ out, Plan pl) {
    extern __shared__ float sm[];
    float* w_sh = sm;            // WSH floats
    float* bufs = sm + WSH;      // nslot * BUF

    const int t  = threadIdx.x;
    const int sq = t & 7;        // 8-sample group
    const int ot = t >> 3;       // output pair 0..31
    const int se = t & 63;       // encode/head sample
    const int og = t >> 6;       // 0..3
    const int gsb = blockIdx.x * TILE;

    float4 wpf[4];
    ldg_w(W1, wpf, t);

    // ---- encode -> bufs[encSlot]: thread (se, og) does 16 features ----
    {
        float* enc = bufs + pl.encSlot * BUF;
        int gs = gsb + se;
        float xs = inp[gs * 3 + 0], ys = inp[gs * 3 + 1], rs = inp[gs * 3 + 2];
        const float4* lp = (const float4*)(lats + gs * 8);
        float4 l0 = lp[0], l1 = lp[1];
#pragma unroll
        for (int i = 0; i < 16; i++) {
            int o = og * 16 + i;
            const float4* wlr = (const float4*)(Wl + o * 8);
            float4 w0 = wlr[0], w1 = wlr[1];
            float pre = __ldg(bl + o);
            pre = fmaf(l0.x, w0.x, pre); pre = fmaf(l0.y, w0.y, pre);
            pre = fmaf(l0.z, w0.z, pre); pre = fmaf(l0.w, w0.w, pre);
            pre = fmaf(l1.x, w1.x, pre); pre = fmaf(l1.y, w1.y, pre);
            pre = fmaf(l1.z, w1.z, pre); pre = fmaf(l1.w, w1.w, pre);
            float lv = fast_tanh(pre);
            float xv = fast_tanh(xs * __ldg(Wx + o));
            float yv; { float z = ys * __ldg(Wy + o); yv = fmaxf(z, 0.f) + __logf(1.f + __expf(-fabsf(z))); }
            float rv; { float z = rs * __ldg(Wr + o); rv = z > 0.f ? z : (__expf(z) - 1.f); }
            float u = xv + yv + rv + lv;
            enc[pidx(o, se)] = __expf(-0.5f * u * u);
        }
    }

    // register accumulator for sink aggregation: 2 feats x 8 samples
    unsigned long long agg[8];
#pragma unroll
    for (int i = 0; i < 8; i++) agg[i] = 0;

    // ---- 17 GEMM steps ----
    for (int st = 0; st < NSTEP; st++) {
        __syncthreads();                  // prev gemm done: w_sh reusable, outputs visible
        sts_w(wpf, w_sh, t);
        if (st < NSTEP - 1) ldg_w(gW + st * 4096, wpf, t);

        int ss = pl.srcSlot[st];
        if (ss < 0) {                     // multi-pred elementwise sum (linear, coalesced)
            int np = pl.nPreds[st];
            const float4* p0 = (const float4*)(bufs + pl.predSlot[st][0] * BUF);
            float4* dst = (float4*)(bufs + pl.sumSlot[st] * BUF);
#pragma unroll 2
            for (int q = t; q < 1024; q += NT) {
                float4 v = p0[q];
                for (int p = 1; p < np; p++) {
                    float4 u = ((const float4*)(bufs + pl.predSlot[st][p] * BUF))[q];
                    v.x += u.x; v.y += u.y; v.z += u.z; v.w += u.w;
                }
                dst[q] = v;
            }
            ss = pl.sumSlot[st];
        }
        __syncthreads();                  // weights + src visible

        // ---- GEMM: 8 samples x 2 outputs per thread ----
        const float* in = bufs + ss * BUF;
        const float* a0 = in + sq * 4;          // even-chunk half
        const float* a1 = in + 32 + sq * 4;     // odd-chunk half
        const float* wq = w_sh + ot * 2;
        unsigned long long c00 = 0, c01 = 0, c02 = 0, c03 = 0;
        unsigned long long c10 = 0, c11 = 0, c12 = 0, c13 = 0;
#pragma unroll 16
        for (int k = 0; k < 64; k++) {
            ulonglong2 x0 = *(const ulonglong2*)(a0 + k * 64);   // samples 8sq..+3
            ulonglong2 x1 = *(const ulonglong2*)(a1 + k * 64);   // samples 8sq+4..+7
            float2 wv = *(const float2*)(wq + k * 64);
            unsigned long long w0 = pk2(wv.x), w1 = pk2(wv.y);
            ffma2(c00, x0.x, w0); ffma2(c01, x0.y, w0);
            ffma2(c02, x1.x, w0); ffma2(c03, x1.y, w0);
            ffma2(c10, x0.x, w1); ffma2(c11, x0.y, w1);
            ffma2(c12, x1.x, w1); ffma2(c13, x1.y, w1);
        }
        const float* bias = (st == 0) ? b1 : gB + (st - 1) * 64;
        float2 bv = *(const float2*)(bias + ot * 2);
        int aid = pl.act[st];
        float f0[8], f1[8];
        upk2(c00, f0[0], f0[1]); upk2(c01, f0[2], f0[3]);
        upk2(c02, f0[4], f0[5]); upk2(c03, f0[6], f0[7]);
        upk2(c10, f1[0], f1[1]); upk2(c11, f1[2], f1[3]);
        upk2(c12, f1[4], f1[5]); upk2(c13, f1[6], f1[7]);
#pragma unroll
        for (int i = 0; i < 8; i++) {
            f0[i] = actf(aid, f0[i] + bv.x);
            f1[i] = actf(aid, f1[i] + bv.y);
        }
        int os = pl.outSlot[st];
        if (os >= 0) {
            float* op = bufs + os * BUF;
            float* q00 = op + (ot * 2) * 64 + sq * 4;
            *(float4*)q00        = make_float4(f0[0], f0[1], f0[2], f0[3]);
            *(float4*)(q00 + 32) = make_float4(f0[4], f0[5], f0[6], f0[7]);
            *(float4*)(q00 + 64) = make_float4(f1[0], f1[1], f1[2], f1[3]);
            *(float4*)(q00 + 96) = make_float4(f1[4], f1[5], f1[6], f1[7]);
        } else {                           // sink: accumulate in registers
            float a, b;
#pragma unroll
            for (int i = 0; i < 4; i++) {
                upk2(agg[i],     a, b); agg[i]     = 0;
                asm("mov.b64 %0, {%1, %2};" : "=l"(agg[i])
                    : "r"(__float_as_uint(a + f0[2*i])), "r"(__float_as_uint(b + f0[2*i+1])));
                upk2(agg[4 + i], a, b); agg[4 + i] = 0;
                asm("mov.b64 %0, {%1, %2};" : "=l"(agg[4+i])
                    : "r"(__float_as_uint(a + f1[2*i])), "r"(__float_as_uint(b + f1[2*i+1])));
            }
        }
    }

    // ---- write register agg to slot 0 (all slots dead now) ----
    __syncthreads();
    {
        float* op = bufs;                  // slot 0 scratch
        float g[16];
        upk2(agg[0], g[0], g[1]);  upk2(agg[1], g[2], g[3]);
        upk2(agg[2], g[4], g[5]);  upk2(agg[3], g[6], g[7]);
        upk2(agg[4], g[8], g[9]);  upk2(agg[5], g[10], g[11]);
        upk2(agg[6], g[12], g[13]); upk2(agg[7], g[14], g[15]);
        float* q00 = op + (ot * 2) * 64 + sq * 4;
        *(float4*)q00        = make_float4(g[0], g[1], g[2], g[3]);
        *(float4*)(q00 + 32) = make_float4(g[4], g[5], g[6], g[7]);
        *(float4*)(q00 + 64) = make_float4(g[8], g[9], g[10], g[11]);
        *(float4*)(q00 + 96) = make_float4(g[12], g[13], g[14], g[15]);
    }
    __syncthreads();

    // ---- head: sigmoid((agg @ outW.T + outb) * scale) ----
    if (og < 3) {
        float acc = __ldg(outb + og);
        const float* wr = outW + og * 64;
        const float* ip = bufs;
#pragma unroll 8
        for (int k = 0; k < 64; k++) acc = fmaf(ip[pidx(k, se)], __ldg(wr + k), acc);
        acc *= __ldg(scale);
        out[(gsb + se) * 3 + og] = __fdividef(1.f, 1.f + __expf(-acc));
    }
}

// ---------------- host: graph replication + slot plan ----------------

namespace {

struct MT19937 {
    uint32_t mt[624];
    int mti;
    void seed(uint32_t sd) {
        mt[0] = sd;
        for (int i = 1; i < 624; i++)
            mt[i] = 1812433253u * (mt[i-1] ^ (mt[i-1] >> 30)) + (uint32_t)i;
        mti = 624;
    }
    uint32_t next32() {
        if (mti >= 624) {
            for (int i = 0; i < 624; i++) {
                uint32_t y = (mt[i] & 0x80000000u) | (mt[(i+1)%624] & 0x7fffffffu);
                uint32_t v = mt[(i+397)%624] ^ (y >> 1);
                if (y & 1u) v ^= 0x9908b0dfu;
                mt[i] = v;
            }
            mti = 0;
        }
        uint32_t y = mt[mti++];
        y ^= y >> 11; y ^= (y << 7) & 0x9d2c5680u;
        y ^= (y << 15) & 0xefc60000u; y ^= y >> 18;
        return y;
    }
    double rnd() {
        uint32_t a = next32() >> 5, b = next32() >> 6;
        return (a * 67108864.0 + b) / 9007199254740992.0;
    }
    uint32_t randint(uint32_t n) {
        uint32_t rng = n - 1;
        if (rng == 0) return 0;
        uint32_t mask = rng;
        mask |= mask >> 1; mask |= mask >> 2; mask |= mask >> 4;
        mask |= mask >> 8; mask |= mask >> 16;
        uint32_t v;
        do { v = next32() & mask; } while (v > rng);
        return v;
    }
};

void build_plan(Plan& P) {
    MT19937 rng; rng.seed(0u);
    const int n = NN;
    bool adj[NN][NN] = {};
    for (int i = 0; i < n; i++)
        for (int d = 1; d <= 2; d++) {
            int j = (i + d) % n;
            if (rng.rnd() < 0.75) j = (int)rng.randint((uint32_t)n);
            int a = i < j ? i : j, b = i < j ? j : i;
            if (a != b) adj[a][b] = true;
        }
    unsigned pm[NN] = {};
    for (int a = 0; a < n; a++)
        for (int b = 0; b < n; b++)
            if (adj[a][b]) pm[b] |= 1u << a;
    for (int j = 1; j < n; j++)
        if (!pm[j]) {
            uint32_t a = rng.randint((uint32_t)j);
            adj[a][j] = true;
            pm[j] |= 1u << a;
        }
    bool isSink[NN];
    for (int j = 0; j < n; j++) {
        bool hs = false;
        for (int b = 0; b < n; b++) if (adj[j][b]) hs = true;
        isSink[j] = !hs;
    }

    int uses[18] = {0};
    uses[17] = 1;
    for (int j = 0; j < n; j++) {
        if (pm[j] == 0) uses[16]++;
        else for (int i = 0; i < n; i++) if ((pm[j] >> i) & 1) uses[i]++;
    }
    int freeS[24], nFree = 0, ns = 0;
    auto alloc = [&]() { return nFree ? freeS[--nFree] : ns++; };
    auto release = [&](int sl) { freeS[nFree++] = sl; };
    int slotOf[18];

    slotOf[17] = alloc();
    P.encSlot = slotOf[17];
    P.srcSlot[0] = slotOf[17]; P.sumSlot[0] = -1; P.nPreds[0] = 0;
    P.act[0] = 3;
    slotOf[16] = alloc();
    P.outSlot[0] = slotOf[16];
    if (--uses[17] == 0) release(slotOf[17]);

    for (int j = 0; j < n; j++) {
        int st = j + 1;
        P.act[st] = j % 5;
        P.sumSlot[st] = -1; P.nPreds[st] = 0;
        int np = 0;
        for (int i = 0; i < n; i++) if ((pm[j] >> i) & 1) np++;

        int srcVal = -1;
        if (np == 0) {
            srcVal = 16;
            P.srcSlot[st] = slotOf[16];
        } else if (np == 1) {
            int p = 0; while (!((pm[j] >> p) & 1)) p++;
            srcVal = p;
            P.srcSlot[st] = slotOf[p];
        } else {
            P.srcSlot[st] = -1; P.nPreds[st] = np;
            int c = 0;
            for (int i = 0; i < n; i++)
                if ((pm[j] >> i) & 1) P.predSlot[st][c++] = (unsigned char)slotOf[i];
            for (int i = 0; i < n; i++)
                if ((pm[j] >> i) & 1) { if (--uses[i] == 0) release(slotOf[i]); }
            P.sumSlot[st] = alloc();
        }

        if (isSink[j]) {
            P.outSlot[st] = -1;               // register aggregation
        } else {
            slotOf[j] = alloc();
            P.outSlot[st] = slotOf[j];
        }

        if (np > 1) release(P.sumSlot[st]);
        else if (--uses[srcVal] == 0) release(slotOf[srcVal]);
    }
    P.nslot = ns;
}

}  // namespace

// ---------------- launch ----------------

extern "C" void kernel_launch(void* const* d_in, const int* in_sizes, int n_in,
                              void* d_out, int out_size) {
    (void)n_in; (void)out_size;
    Plan pl;
    build_plan(pl);

    const int B = in_sizes[0] / 3;
    const int ntiles = B / TILE;

    const size_t smem = (size_t)(WSH + pl.nslot * BUF) * sizeof(float);
    cudaFuncSetAttribute(inr_kernel, cudaFuncAttributeMaxDynamicSharedMemorySize,
                         (int)smem);

    inr_kernel<<<ntiles, NT, smem>>>(
        (const float*)d_in[0],  (const float*)d_in[1],  (const float*)d_in[2],
        (const float*)d_in[3],  (const float*)d_in[4],  (const float*)d_in[5],
        (const float*)d_in[6],  (const float*)d_in[7],  (const float*)d_in[8],
        (const float*)d_in[9],  (const float*)d_in[10], (const float*)d_in[11],
        (const float*)d_in[12], (const float*)d_in[13], (float*)d_out, pl);
}

// round 10
// speedup vs baseline: 1.2877x; 1.1816x over previous
#include <cuda_runtime.h>
#include <cstdint>

#define NN 16
#define NSTEP 17
#define BMAX 131072
#define CTA_S 128
#define NT 256
#define MAXSLOT 12

// static scratch: feature-major [64][BMAX] activation buffers + transposed weights
__device__ float g_slot[MAXSLOT][64 * BMAX];
__device__ float g_wt[NSTEP][4096];          // [k][o]

struct Plan {
    int nslot;
    int encSlot, aggSlot;
    int srcSlot[NSTEP];
    int sumSlot[NSTEP];
    int outSlot[NSTEP];
    int accum[NSTEP];
    int act[NSTEP];
    int nPreds[NSTEP];
    unsigned char predSlot[NSTEP][NN];
};

// ---------------- helpers ----------------

__device__ __forceinline__ unsigned long long pk2(float x) {
    unsigned long long r; unsigned xi = __float_as_uint(x);
    asm("mov.b64 %0, {%1, %1};" : "=l"(r) : "r"(xi));
    return r;
}
__device__ __forceinline__ void upk2(unsigned long long v, float& lo, float& hi) {
    unsigned a, b;
    asm("mov.b64 {%0, %1}, %2;" : "=r"(a), "=r"(b) : "l"(v));
    lo = __uint_as_float(a); hi = __uint_as_float(b);
}
__device__ __forceinline__ void ffma2(unsigned long long& acc,
                                      unsigned long long a, unsigned long long b) {
    asm("fma.rn.f32x2 %0, %1, %2, %0;" : "+l"(acc) : "l"(a), "l"(b));
}
__device__ __forceinline__ float fast_tanh(float x) {
    float e = __expf(2.f * x);
    return 1.f - __fdividef(2.f, e + 1.f);
}
// GRAPH_ACTS = [tanh, elu, softplus, sin, gaussian]
__device__ __forceinline__ float actf(int id, float v) {
    switch (id) {
        case 0:  return fast_tanh(v);
        case 1:  return v > 0.f ? v : (__expf(v) - 1.f);
        case 2:  return fmaxf(v, 0.f) + __logf(1.f + __expf(-fabsf(v)));
        case 3:  return __sinf(v);
        default: return __expf(-0.5f * v * v);
    }
}

// ---------------- weight transpose kernel: g_wt[l][k*64+o] = W_l[o][k] ----------------

__global__ void wt_kernel(const float* __restrict__ W1, const float* __restrict__ gW) {
    int l = blockIdx.x;
    const float* src = (l == 0) ? W1 : gW + (l - 1) * 4096;
    float* dst = g_wt[l];
    for (int i = threadIdx.x; i < 4096; i += blockDim.x) {
        int o = i >> 6, k = i & 63;
        dst[k * 64 + o] = src[i];
    }
}

// ---------------- main kernel ----------------

__global__ void __launch_bounds__(NT, 2)
inr_kernel(const float* __restrict__ inp, const float* __restrict__ lats,
           const float* __restrict__ Wl, const float* __restrict__ bl,
           const float* __restrict__ Wx, const float* __restrict__ Wy,
           const float* __restrict__ Wr, const float* __restrict__ b1,
           const float* __restrict__ gB, const float* __restrict__ outW,
           const float* __restrict__ outb, const float* __restrict__ scale,
           float* __restrict__ out, Plan pl) {
    const int t    = threadIdx.x;
    const int og   = t >> 5;                 // warp owns outputs og*8..og*8+7
    const int lane = t & 31;
    const int sb   = blockIdx.x * CTA_S;
    const int s0   = sb + lane * 4;          // this lane's 4 samples

    // ---- encode -> g_slot[encSlot] ----
    {
        float* enc = g_slot[pl.encSlot];
        float xs[4], ys[4], rs[4], lat[4][8];
#pragma unroll
        for (int j = 0; j < 4; j++) {
            int gs = s0 + j;
            xs[j] = inp[gs * 3 + 0]; ys[j] = inp[gs * 3 + 1]; rs[j] = inp[gs * 3 + 2];
            const float4* lp = (const float4*)(lats + gs * 8);
            float4 l0 = lp[0], l1 = lp[1];
            lat[j][0]=l0.x; lat[j][1]=l0.y; lat[j][2]=l0.z; lat[j][3]=l0.w;
            lat[j][4]=l1.x; lat[j][5]=l1.y; lat[j][6]=l1.z; lat[j][7]=l1.w;
        }
#pragma unroll
        for (int i = 0; i < 8; i++) {
            int o = og * 8 + i;
            const float4* wlr = (const float4*)(Wl + o * 8);
            float4 w0 = wlr[0], w1 = wlr[1];
            float blo = __ldg(bl + o), wx = __ldg(Wx + o);
            float wy = __ldg(Wy + o), wr = __ldg(Wr + o);
            float v[4];
#pragma unroll
            for (int j = 0; j < 4; j++) {
                float pre = blo;
                pre = fmaf(lat[j][0], w0.x, pre); pre = fmaf(lat[j][1], w0.y, pre);
                pre = fmaf(lat[j][2], w0.z, pre); pre = fmaf(lat[j][3], w0.w, pre);
                pre = fmaf(lat[j][4], w1.x, pre); pre = fmaf(lat[j][5], w1.y, pre);
                pre = fmaf(lat[j][6], w1.z, pre); pre = fmaf(lat[j][7], w1.w, pre);
                float lv = fast_tanh(pre);
                float xv = fast_tanh(xs[j] * wx);
                float yv; { float z = ys[j] * wy; yv = fmaxf(z, 0.f) + __logf(1.f + __expf(-fabsf(z))); }
                float rv; { float z = rs[j] * wr; rv = z > 0.f ? z : (__expf(z) - 1.f); }
                float u = xv + yv + rv + lv;
                v[j] = __expf(-0.5f * u * u);
            }
            *(float4*)(enc + o * BMAX + s0) = make_float4(v[0], v[1], v[2], v[3]);
        }
    }

    // ---- 17 layers ----
    for (int st = 0; st < NSTEP; st++) {
        __syncthreads();                       // previous layer's stores visible (same CTA)

        int ss = pl.srcSlot[st];
        if (ss < 0) {                          // multi-pred elementwise sum
            int np = pl.nPreds[st];
            float* dst = g_slot[pl.sumSlot[st]];
#pragma unroll
            for (int i = 0; i < 8; i++) {
                int off = (og * 8 + i) * BMAX + s0;
                float4 v = *(const float4*)(g_slot[pl.predSlot[st][0]] + off);
                for (int p = 1; p < np; p++) {
                    float4 u = *(const float4*)(g_slot[pl.predSlot[st][p]] + off);
                    v.x += u.x; v.y += u.y; v.z += u.z; v.w += u.w;
                }
                *(float4*)(dst + off) = v;
            }
            ss = pl.sumSlot[st];
            __syncthreads();
        }

        // ---- GEMM: warp computes outputs og*8..+7 for its lanes' 4 samples ----
        const float* src = g_slot[ss] + s0;
        const float* wt  = g_wt[st] + og * 8;   // [k][o] pairs packed
        unsigned long long acc[4][4];
#pragma unroll
        for (int op = 0; op < 4; op++)
#pragma unroll
            for (int j = 0; j < 4; j++) acc[op][j] = 0;

#pragma unroll 4
        for (int k = 0; k < 64; k++) {
            float4 av = *(const float4*)(src + (size_t)k * BMAX);
            ulonglong2 wA = *(const ulonglong2*)(wt + k * 64);       // (w0,w1),(w2,w3)
            ulonglong2 wB = *(const ulonglong2*)(wt + k * 64 + 4);   // (w4,w5),(w6,w7)
            unsigned long long a0 = pk2(av.x), a1 = pk2(av.y);
            unsigned long long a2 = pk2(av.z), a3 = pk2(av.w);
            ffma2(acc[0][0], a0, wA.x); ffma2(acc[0][1], a1, wA.x);
            ffma2(acc[0][2], a2, wA.x); ffma2(acc[0][3], a3, wA.x);
            ffma2(acc[1][0], a0, wA.y); ffma2(acc[1][1], a1, wA.y);
            ffma2(acc[1][2], a2, wA.y); ffma2(acc[1][3], a3, wA.y);
            ffma2(acc[2][0], a0, wB.x); ffma2(acc[2][1], a1, wB.x);
            ffma2(acc[2][2], a2, wB.x); ffma2(acc[2][3], a3, wB.x);
            ffma2(acc[3][0], a0, wB.y); ffma2(acc[3][1], a1, wB.y);
            ffma2(acc[3][2], a2, wB.y); ffma2(acc[3][3], a3, wB.y);
        }

        // ---- epilogue: bias + activation + store ----
        const float* bias = (st == 0) ? b1 : gB + (st - 1) * 64;
        float4 bA = *(const float4*)(bias + og * 8);
        float4 bB = *(const float4*)(bias + og * 8 + 4);
        float bb[8] = {bA.x, bA.y, bA.z, bA.w, bB.x, bB.y, bB.z, bB.w};
        int os = pl.outSlot[st];
        bool acm = pl.accum[st] != 0;
        int aid = pl.act[st];
        float* ob = g_slot[os];
#pragma unroll
        for (int op = 0; op < 4; op++) {
            float e[4], o_[4];
#pragma unroll
            for (int j = 0; j < 4; j++) upk2(acc[op][j], e[j], o_[j]);
            float4 ve, vo;
            ve.x = actf(aid, e[0] + bb[2*op]);   ve.y = actf(aid, e[1] + bb[2*op]);
            ve.z = actf(aid, e[2] + bb[2*op]);   ve.w = actf(aid, e[3] + bb[2*op]);
            vo.x = actf(aid, o_[0] + bb[2*op+1]); vo.y = actf(aid, o_[1] + bb[2*op+1]);
            vo.z = actf(aid, o_[2] + bb[2*op+1]); vo.w = actf(aid, o_[3] + bb[2*op+1]);
            float* pe = ob + (og * 8 + 2 * op) * BMAX + s0;
            float* po = pe + BMAX;
            if (acm) {
                float4 ce = *(const float4*)pe, co = *(const float4*)po;
                ve.x += ce.x; ve.y += ce.y; ve.z += ce.z; ve.w += ce.w;
                vo.x += co.x; vo.y += co.y; vo.z += co.z; vo.w += co.w;
            }
            *(float4*)pe = ve;
            *(float4*)po = vo;
        }
    }
    __syncthreads();

    // ---- head: sigmoid((agg @ outW.T + outb) * scale) ----
    if (t < CTA_S) {
        int gs = sb + t;
        const float* ag = g_slot[pl.aggSlot] + gs;
        float a0 = __ldg(outb + 0), a1 = __ldg(outb + 1), a2 = __ldg(outb + 2);
#pragma unroll 8
        for (int k = 0; k < 64; k++) {
            float a = ag[(size_t)k * BMAX];
            a0 = fmaf(a, __ldg(outW + k), a0);
            a1 = fmaf(a, __ldg(outW + 64 + k), a1);
            a2 = fmaf(a, __ldg(outW + 128 + k), a2);
        }
        float sc = __ldg(scale);
        out[gs * 3 + 0] = __fdividef(1.f, 1.f + __expf(-a0 * sc));
        out[gs * 3 + 1] = __fdividef(1.f, 1.f + __expf(-a1 * sc));
        out[gs * 3 + 2] = __fdividef(1.f, 1.f + __expf(-a2 * sc));
    }
}

// ---------------- host: graph replication + slot plan ----------------

namespace {

struct MT19937 {
    uint32_t mt[624];
    int mti;
    void seed(uint32_t sd) {
        mt[0] = sd;
        for (int i = 1; i < 624; i++)
            mt[i] = 1812433253u * (mt[i-1] ^ (mt[i-1] >> 30)) + (uint32_t)i;
        mti = 624;
    }
    uint32_t next32() {
        if (mti >= 624) {
            for (int i = 0; i < 624; i++) {
                uint32_t y = (mt[i] & 0x80000000u) | (mt[(i+1)%624] & 0x7fffffffu);
                uint32_t v = mt[(i+397)%624] ^ (y >> 1);
                if (y & 1u) v ^= 0x9908b0dfu;
                mt[i] = v;
            }
            mti = 0;
        }
        uint32_t y = mt[mti++];
        y ^= y >> 11; y ^= (y << 7) & 0x9d2c5680u;
        y ^= (y << 15) & 0xefc60000u; y ^= y >> 18;
        return y;
    }
    double rnd() {
        uint32_t a = next32() >> 5, b = next32() >> 6;
        return (a * 67108864.0 + b) / 9007199254740992.0;
    }
    uint32_t randint(uint32_t n) {
        uint32_t rng = n - 1;
        if (rng == 0) return 0;
        uint32_t mask = rng;
        mask |= mask >> 1; mask |= mask >> 2; mask |= mask >> 4;
        mask |= mask >> 8; mask |= mask >> 16;
        uint32_t v;
        do { v = next32() & mask; } while (v > rng);
        return v;
    }
};

void build_plan(Plan& P) {
    MT19937 rng; rng.seed(0u);
    const int n = NN;
    bool adj[NN][NN] = {};
    for (int i = 0; i < n; i++)
        for (int d = 1; d <= 2; d++) {
            int j = (i + d) % n;
            if (rng.rnd() < 0.75) j = (int)rng.randint((uint32_t)n);
            int a = i < j ? i : j, b = i < j ? j : i;
            if (a != b) adj[a][b] = true;
        }
    unsigned pm[NN] = {};
    for (int a = 0; a < n; a++)
        for (int b = 0; b < n; b++)
            if (adj[a][b]) pm[b] |= 1u << a;
    for (int j = 1; j < n; j++)
        if (!pm[j]) {
            uint32_t a = rng.randint((uint32_t)j);
            adj[a][j] = true;
            pm[j] |= 1u << a;
        }
    bool isSink[NN];
    for (int j = 0; j < n; j++) {
        bool hs = false;
        for (int b = 0; b < n; b++) if (adj[j][b]) hs = true;
        isSink[j] = !hs;
    }

    int uses[18] = {0};
    uses[17] = 1;
    for (int j = 0; j < n; j++) {
        if (pm[j] == 0) uses[16]++;
        else for (int i = 0; i < n; i++) if ((pm[j] >> i) & 1) uses[i]++;
    }
    int freeS[24], nFree = 0, ns = 0;
    auto alloc = [&]() { return nFree ? freeS[--nFree] : ns++; };
    auto release = [&](int sl) { freeS[nFree++] = sl; };
    int slotOf[18];

    P.aggSlot = -1;
    slotOf[17] = alloc();
    P.encSlot = slotOf[17];

    P.srcSlot[0] = slotOf[17]; P.sumSlot[0] = -1; P.nPreds[0] = 0;
    P.act[0] = 3; P.accum[0] = 0;
    slotOf[16] = alloc();
    P.outSlot[0] = slotOf[16];
    if (--uses[17] == 0) release(slotOf[17]);

    for (int j = 0; j < n; j++) {
        int st = j + 1;
        P.act[st] = j % 5;
        P.sumSlot[st] = -1; P.nPreds[st] = 0;
        int np = 0;
        for (int i = 0; i < n; i++) if ((pm[j] >> i) & 1) np++;

        int srcVal = -1;
        if (np == 0) {
            srcVal = 16;
            P.srcSlot[st] = slotOf[16];
        } else if (np == 1) {
            int p = 0; while (!((pm[j] >> p) & 1)) p++;
            srcVal = p;
            P.srcSlot[st] = slotOf[p];
        } else {
            P.srcSlot[st] = -1; P.nPreds[st] = np;
            int c = 0;
            for (int i = 0; i < n; i++)
                if ((pm[j] >> i) & 1) P.predSlot[st][c++] = (unsigned char)slotOf[i];
            for (int i = 0; i < n; i++)
                if ((pm[j] >> i) & 1) { if (--uses[i] == 0) release(slotOf[i]); }
            P.sumSlot[st] = alloc();
        }

        if (isSink[j]) {
            if (P.aggSlot < 0) { P.aggSlot = alloc(); P.accum[st] = 0; }
            else P.accum[st] = 1;
            P.outSlot[st] = P.aggSlot;
        } else {
            P.accum[st] = 0;
            slotOf[j] = alloc();
            P.outSlot[st] = slotOf[j];
        }

        if (np > 1) release(P.sumSlot[st]);
        else if (--uses[srcVal] == 0) release(slotOf[srcVal]);
    }
    P.nslot = ns;
}

}  // namespace

// ---------------- launch ----------------

extern "C" void kernel_launch(void* const* d_in, const int* in_sizes, int n_in,
                              void* d_out, int out_size) {
    (void)n_in; (void)out_size;
    Plan pl;
    build_plan(pl);

    const int B = in_sizes[0] / 3;
    const int ntiles = B / CTA_S;

    // stage transposed weights ([k][o]) for W1 + 16 graph nodes
    wt_kernel<<<NSTEP, 256>>>((const float*)d_in[7], (const float*)d_in[9]);

    inr_kernel<<<ntiles, NT>>>(
        (const float*)d_in[0],  (const float*)d_in[1],  (const float*)d_in[2],
        (const float*)d_in[3],  (const float*)d_in[4],  (const float*)d_in[5],
        (const float*)d_in[6],  (const float*)d_in[8],  (const float*)d_in[10],
        (const float*)d_in[11], (const float*)d_in[12], (const float*)d_in[13],
        (float*)d_out, pl);
}